// round 7
// baseline (speedup 1.0000x reference)
#include <cuda_runtime.h>
#include <cuda_bf16.h>

// Problem constants (fixed shapes per reference)
#define NN_MAX 50000
#define EE_MAX 800000

// ---------------- scratch (device globals; no runtime allocation) ----------------
__device__ float g_Q1[NN_MAX * 128];
__device__ float g_K1[NN_MAX * 128];
__device__ float g_V1[NN_MAX * 128];
__device__ float g_S1[NN_MAX * 128];
__device__ float g_h [NN_MAX * 128];
__device__ float g_Q2[NN_MAX * 64];
__device__ float g_K2[NN_MAX * 64];
__device__ float g_V2[NN_MAX * 64];
__device__ float g_S2[NN_MAX * 64];

__device__ int g_cnt[NN_MAX];
__device__ int g_rowptr[NN_MAX + 1];
__device__ int g_cur[NN_MAX];
__device__ int g_psrc[EE_MAX];

// ---------------- CSR build ----------------
__global__ void k_zero(int n) {
    int i = blockIdx.x * blockDim.x + threadIdx.x;
    if (i < n) g_cnt[i] = 0;
}

__global__ void k_hist(const int* __restrict__ dst, int e) {
    int i = blockIdx.x * blockDim.x + threadIdx.x;
    if (i < e) atomicAdd(&g_cnt[dst[i]], 1);
}

// Chunked 2-pass scan: each of 1024 threads owns a contiguous chunk.
__global__ __launch_bounds__(1024) void k_scan(int n) {
    int tid = threadIdx.x;
    int CH = (n + 1023) >> 10;
    int base = tid * CH;
    int lim = min(base + CH, n);

    int sum = 0;
    for (int i = base; i < lim; i++) sum += g_cnt[i];

    int lane = tid & 31, wid = tid >> 5;
    int v = sum;
    #pragma unroll
    for (int off = 1; off < 32; off <<= 1) {
        int t = __shfl_up_sync(0xffffffffu, v, off);
        if (lane >= off) v += t;
    }
    __shared__ int wsum[32];
    if (lane == 31) wsum[wid] = v;
    __syncthreads();
    if (wid == 0) {
        int w = wsum[lane];
        #pragma unroll
        for (int off = 1; off < 32; off <<= 1) {
            int t = __shfl_up_sync(0xffffffffu, w, off);
            if (lane >= off) w += t;
        }
        wsum[lane] = w;
    }
    __syncthreads();
    int excl = v - sum + (wid ? wsum[wid - 1] : 0);

    int run = excl;
    for (int i = base; i < lim; i++) {
        int c = g_cnt[i];
        g_rowptr[i] = run;
        g_cur[i] = run;
        run += c;
    }
    if (tid == 1023) g_rowptr[n] = run;
}

__global__ void k_scatter(const int* __restrict__ src, const int* __restrict__ dst, int e) {
    int i = blockIdx.x * blockDim.x + threadIdx.x;
    if (i < e) {
        int d = dst[i];
        int pos = atomicAdd(&g_cur[d], 1);
        g_psrc[pos] = src[i];
    }
}

// ---------------- tensor-core GEMM: (M x 128) @ (128 x Ncols) + bias ----------------
// split-bf16 (3xBF16): x = hi + lo (bf16 each), C = Ah*Bh + Ah*Bl + Al*Bh.
// ~16 mantissa bits effective -> rel_err ~1e-5. mma.m16n8k16 -> half the mma count of tf32-k8.
// Tile: BM=128, BN=64, BK=16. 256 threads = 8 warps (4 row x 2 col), warp tile 32x32.

__device__ __forceinline__ float* sel_out(int s) {
    switch (s) {
        case 0: return g_Q1; case 1: return g_K1; case 2: return g_V1; case 3: return g_S1;
        case 4: return g_Q2; case 5: return g_K2; case 6: return g_V2; default: return g_S2;
    }
}

// Split a pair of consecutive-k floats into packed bf16 hi and lo words.
// Low 16 bits = even k element (matches mma fragment layout).
__device__ __forceinline__ void split_pair(float a, float b, unsigned& hi, unsigned& lo) {
    __nv_bfloat16 ah = __float2bfloat16_rn(a);
    __nv_bfloat16 bh = __float2bfloat16_rn(b);
    float ar = a - __bfloat162float(ah);
    float br = b - __bfloat162float(bh);
    __nv_bfloat162 hp = __halves2bfloat162(ah, bh);
    __nv_bfloat162 lp = __floats2bfloat162_rn(ar, br);
    hi = *reinterpret_cast<unsigned*>(&hp);
    lo = *reinterpret_cast<unsigned*>(&lp);
}

__device__ __forceinline__ void mma16816(float& c0, float& c1, float& c2, float& c3,
                                         unsigned a0, unsigned a1, unsigned a2, unsigned a3,
                                         unsigned b0, unsigned b1) {
    asm volatile("mma.sync.aligned.m16n8k16.row.col.f32.bf16.bf16.f32 "
                 "{%0,%1,%2,%3}, {%4,%5,%6,%7}, {%8,%9}, {%0,%1,%2,%3};"
                 : "+f"(c0), "+f"(c1), "+f"(c2), "+f"(c3)
                 : "r"(a0), "r"(a1), "r"(a2), "r"(a3), "r"(b0), "r"(b1));
}

#define ARS 12   // uint stride per A row (8 kpairs + 4 pad): 4g+t distinct mod 32
#define BRS 12   // uint stride per B col

__global__ __launch_bounds__(256) void gemm_tc(const float* __restrict__ Ain,
                                               const float* __restrict__ W0, const float* __restrict__ W1,
                                               const float* __restrict__ W2, const float* __restrict__ W3,
                                               const float* __restrict__ b0p, const float* __restrict__ b1p,
                                               const float* __restrict__ b2p, const float* __restrict__ b3p,
                                               int M, int Ncols, int outBase)
{
    const float* A = Ain ? Ain : g_h;
    int z = blockIdx.z;
    const float* W    = (z == 0) ? W0  : (z == 1) ? W1  : (z == 2) ? W2  : W3;
    const float* bias = (z == 0) ? b0p : (z == 1) ? b1p : (z == 2) ? b2p : b3p;
    float* C = sel_out(outBase + z);

    __shared__ unsigned Ah[128 * ARS], Al[128 * ARS];
    __shared__ unsigned Bh[64 * BRS],  Bl[64 * BRS];

    int tid  = threadIdx.x;
    int lane = tid & 31;
    int w    = tid >> 5;
    int rowW = (w & 3) * 32;
    int colW = (w >> 2) * 32;
    int g = lane >> 2, t = lane & 3;

    int rowBase = blockIdx.y * 128;
    int colBase = blockIdx.x * 64;

    float acc[2][4][4];
    #pragma unroll
    for (int mi = 0; mi < 2; mi++)
        #pragma unroll
        for (int ni = 0; ni < 4; ni++)
            #pragma unroll
            for (int r = 0; r < 4; r++) acc[mi][ni][r] = 0.f;

    for (int kk = 0; kk < 128; kk += 16) {
        // fill A planes: 128x16 floats = 512 float4, 2 per thread
        #pragma unroll
        for (int i = 0; i < 2; i++) {
            int idx = tid + i * 256;           // 0..511
            int row = idx >> 2;                // 0..127
            int c4  = (idx & 3) * 4;           // 0,4,8,12
            int kp  = (idx & 3) * 2;           // kpair index 0,2,4,6
            int gr  = rowBase + row;
            float4 av = make_float4(0.f, 0.f, 0.f, 0.f);
            if (gr < M) av = *(const float4*)(A + (size_t)gr * 128 + kk + c4);
            unsigned h0, l0, h1, l1;
            split_pair(av.x, av.y, h0, l0);
            split_pair(av.z, av.w, h1, l1);
            Ah[row * ARS + kp]     = h0;  Al[row * ARS + kp]     = l0;
            Ah[row * ARS + kp + 1] = h1;  Al[row * ARS + kp + 1] = l1;
        }
        // fill B planes: 16k x 64n = 512 kpairs, 2 per thread (coalesced along col)
        #pragma unroll
        for (int i = 0; i < 2; i++) {
            int p   = tid + i * 256;           // 0..511
            int col = p & 63;
            int kp  = p >> 6;                  // 0..7
            float be = W[(size_t)(kk + 2 * kp)     * Ncols + colBase + col];
            float bo = W[(size_t)(kk + 2 * kp + 1) * Ncols + colBase + col];
            unsigned hb, lb;
            split_pair(be, bo, hb, lb);
            Bh[col * BRS + kp] = hb;  Bl[col * BRS + kp] = lb;
        }
        __syncthreads();

        // A fragments (hi + lo planes)
        unsigned ah[2][4], al[2][4];
        #pragma unroll
        for (int mi = 0; mi < 2; mi++) {
            int r0 = rowW + mi * 16 + g;
            ah[mi][0] = Ah[(r0    ) * ARS + t];     al[mi][0] = Al[(r0    ) * ARS + t];
            ah[mi][1] = Ah[(r0 + 8) * ARS + t];     al[mi][1] = Al[(r0 + 8) * ARS + t];
            ah[mi][2] = Ah[(r0    ) * ARS + t + 4]; al[mi][2] = Al[(r0    ) * ARS + t + 4];
            ah[mi][3] = Ah[(r0 + 8) * ARS + t + 4]; al[mi][3] = Al[(r0 + 8) * ARS + t + 4];
        }
        // B fragments
        unsigned bh[4][2], bl[4][2];
        #pragma unroll
        for (int ni = 0; ni < 4; ni++) {
            int col = colW + ni * 8 + g;
            bh[ni][0] = Bh[col * BRS + t];     bl[ni][0] = Bl[col * BRS + t];
            bh[ni][1] = Bh[col * BRS + t + 4]; bl[ni][1] = Bl[col * BRS + t + 4];
        }
        // 3xBF16: hi*hi + hi*lo + lo*hi
        #pragma unroll
        for (int mi = 0; mi < 2; mi++) {
            #pragma unroll
            for (int ni = 0; ni < 4; ni++) {
                float* c = acc[mi][ni];
                mma16816(c[0], c[1], c[2], c[3],
                         ah[mi][0], ah[mi][1], ah[mi][2], ah[mi][3],
                         bh[ni][0], bh[ni][1]);
                mma16816(c[0], c[1], c[2], c[3],
                         ah[mi][0], ah[mi][1], ah[mi][2], ah[mi][3],
                         bl[ni][0], bl[ni][1]);
                mma16816(c[0], c[1], c[2], c[3],
                         al[mi][0], al[mi][1], al[mi][2], al[mi][3],
                         bh[ni][0], bh[ni][1]);
            }
        }
        __syncthreads();
    }

    // epilogue: bias + store
    #pragma unroll
    for (int ni = 0; ni < 4; ni++) {
        int col = colBase + colW + ni * 8 + 2 * t;
        float bx = bias[col], by = bias[col + 1];
        #pragma unroll
        for (int mi = 0; mi < 2; mi++) {
            int r0 = rowBase + rowW + mi * 16 + g;
            float* c = acc[mi][ni];
            if (r0 < M) {
                float2 o = make_float2(c[0] + bx, c[1] + by);
                *(float2*)(C + (size_t)r0 * Ncols + col) = o;
            }
            if (r0 + 8 < M) {
                float2 o = make_float2(c[2] + bx, c[3] + by);
                *(float2*)(C + (size_t)(r0 + 8) * Ncols + col) = o;
            }
        }
    }
}

// ---------------- layer-1 aggregation: warp per node, online softmax, H=8 D=16 ----------------
// 2-deep software pipeline: K/V gathers for edge e+2 issued while computing edge e.
__global__ __launch_bounds__(256) void agg1_kernel(int Nn)
{
    int warp = (blockIdx.x * blockDim.x + threadIdx.x) >> 5;
    int lane = threadIdx.x & 31;
    if (warp >= Nn) return;
    int n = warp;

    const float4* Q4 = (const float4*)g_Q1;
    const float4* K4 = (const float4*)g_K1;
    const float4* V4 = (const float4*)g_V1;
    const float4* S4 = (const float4*)g_S1;

    float4 q = Q4[(size_t)n * 32 + lane];

    int beg = g_rowptr[n];
    int end = g_rowptr[n + 1];

    float m = -1e30f, s = 0.f;
    float4 acc = make_float4(0.f, 0.f, 0.f, 0.f);

    if (beg < end) {
        int s0 = g_psrc[beg];
        float4 kA = K4[(size_t)s0 * 32 + lane];
        float4 vA = V4[(size_t)s0 * 32 + lane];
        float4 kB = kA, vB = vA;
        if (beg + 1 < end) {
            int s1 = g_psrc[beg + 1];
            kB = K4[(size_t)s1 * 32 + lane];
            vB = V4[(size_t)s1 * 32 + lane];
        }
        for (int e = beg; e < end; e++) {
            float4 kC = kA, vC = vA;
            if (e + 2 < end) {
                int s2 = g_psrc[e + 2];
                kC = K4[(size_t)s2 * 32 + lane];
                vC = V4[(size_t)s2 * 32 + lane];
            }

            float d = kA.x * q.x + kA.y * q.y + kA.z * q.z + kA.w * q.w;
            d += __shfl_xor_sync(0xffffffffu, d, 1);
            d += __shfl_xor_sync(0xffffffffu, d, 2);   // reduce within 4-lane head group
            float sc = d * 0.25f;                       // 1/sqrt(16)

            float mn = fmaxf(m, sc);
            float c  = __expf(m - mn);
            float p  = __expf(sc - mn);
            s = s * c + p;
            acc.x = acc.x * c + p * vA.x;
            acc.y = acc.y * c + p * vA.y;
            acc.z = acc.z * c + p * vA.z;
            acc.w = acc.w * c + p * vA.w;
            m = mn;

            kA = kB; vA = vB; kB = kC; vB = vC;
        }
    }

    float inv = 1.f / (s + 1e-16f);
    float4 sk = S4[(size_t)n * 32 + lane];
    float4 o;
    o.x = fmaxf(acc.x * inv + sk.x, 0.f);
    o.y = fmaxf(acc.y * inv + sk.y, 0.f);
    o.z = fmaxf(acc.z * inv + sk.z, 0.f);
    o.w = fmaxf(acc.w * inv + sk.w, 0.f);
    ((float4*)g_h)[(size_t)n * 32 + lane] = o;
}

// ---------------- layer-2 aggregation: warp per node, online softmax, H=1 D=64 ----------------
__global__ __launch_bounds__(256) void agg2_kernel(float* __restrict__ out, int Nn)
{
    int warp = (blockIdx.x * blockDim.x + threadIdx.x) >> 5;
    int lane = threadIdx.x & 31;
    if (warp >= Nn) return;
    int n = warp;

    const float2* Q2 = (const float2*)g_Q2;
    const float2* K2 = (const float2*)g_K2;
    const float2* V2 = (const float2*)g_V2;
    const float2* S2 = (const float2*)g_S2;

    float2 q = Q2[(size_t)n * 32 + lane];

    int beg = g_rowptr[n];
    int end = g_rowptr[n + 1];

    float m = -1e30f, s = 0.f;
    float2 acc = make_float2(0.f, 0.f);

    if (beg < end) {
        int s0 = g_psrc[beg];
        float2 kA = K2[(size_t)s0 * 32 + lane];
        float2 vA = V2[(size_t)s0 * 32 + lane];
        float2 kB = kA, vB = vA;
        if (beg + 1 < end) {
            int s1 = g_psrc[beg + 1];
            kB = K2[(size_t)s1 * 32 + lane];
            vB = V2[(size_t)s1 * 32 + lane];
        }
        for (int e = beg; e < end; e++) {
            float2 kC = kA, vC = vA;
            if (e + 2 < end) {
                int s2 = g_psrc[e + 2];
                kC = K2[(size_t)s2 * 32 + lane];
                vC = V2[(size_t)s2 * 32 + lane];
            }

            float d = kA.x * q.x + kA.y * q.y;
            #pragma unroll
            for (int off = 16; off > 0; off >>= 1)
                d += __shfl_xor_sync(0xffffffffu, d, off);
            float sc = d * 0.125f;                      // 1/sqrt(64)

            float mn = fmaxf(m, sc);
            float c  = __expf(m - mn);
            float p  = __expf(sc - mn);
            s = s * c + p;
            acc.x = acc.x * c + p * vA.x;
            acc.y = acc.y * c + p * vA.y;
            m = mn;

            kA = kB; vA = vB; kB = kC; vB = vC;
        }
    }

    float inv = 1.f / (s + 1e-16f);
    float2 sk = S2[(size_t)n * 32 + lane];
    float2 o;
    o.x = acc.x * inv + sk.x;
    o.y = acc.y * inv + sk.y;
    ((float2*)out)[(size_t)n * 32 + lane] = o;
}

// ---------------- launch ----------------
extern "C" void kernel_launch(void* const* d_in, const int* in_sizes, int n_in,
                              void* d_out, int out_size)
{
    const float* x   = (const float*)d_in[0];
    const float* Wq1 = (const float*)d_in[1];  const float* bq1 = (const float*)d_in[2];
    const float* Wk1 = (const float*)d_in[3];  const float* bk1 = (const float*)d_in[4];
    const float* Wv1 = (const float*)d_in[5];  const float* bv1 = (const float*)d_in[6];
    const float* Ws1 = (const float*)d_in[7];  const float* bs1 = (const float*)d_in[8];
    const float* Wq2 = (const float*)d_in[9];  const float* bq2 = (const float*)d_in[10];
    const float* Wk2 = (const float*)d_in[11]; const float* bk2 = (const float*)d_in[12];
    const float* Wv2 = (const float*)d_in[13]; const float* bv2 = (const float*)d_in[14];
    const float* Ws2 = (const float*)d_in[15]; const float* bs2 = (const float*)d_in[16];
    const int* esrc  = (const int*)d_in[17];
    const int* edst  = (const int*)d_in[18];
    float* out = (float*)d_out;

    int Nn = in_sizes[0] / 128;
    int E  = in_sizes[17];

    // CSR build (per launch; replayed identically by the graph)
    k_zero<<<(Nn + 255) / 256, 256>>>(Nn);
    k_hist<<<(E + 255) / 256, 256>>>(edst, E);
    k_scan<<<1, 1024>>>(Nn);
    k_scatter<<<(E + 255) / 256, 256>>>(esrc, edst, E);

    // layer-1 projections: [N,128] @ [128,128] + b   (Q,K,V,S via blockIdx.z)
    dim3 g1(128 / 64, (Nn + 127) / 128, 4);
    gemm_tc<<<g1, 256>>>(x, Wq1, Wk1, Wv1, Ws1, bq1, bk1, bv1, bs1, Nn, 128, 0);

    int aggBlocks = (Nn + 7) / 8;   // 8 warps per 256-thread block
    agg1_kernel<<<aggBlocks, 256>>>(Nn);

    // layer-2 projections: [N,128] @ [128,64] + b (A = g_h via nullptr)
    dim3 g2(1, (Nn + 127) / 128, 4);
    gemm_tc<<<g2, 256>>>(nullptr, Wq2, Wk2, Wv2, Ws2, bq2, bk2, bv2, bs2, Nn, 64, 4);

    agg2_kernel<<<aggBlocks, 256>>>(out, Nn);
}